// round 1
// baseline (speedup 1.0000x reference)
#include <cuda_runtime.h>
#include <math.h>

#define BATCH 96
#define C 64
#define N 512
#define O 64
#define KM 10
#define KC 8
#define EPSBN 1e-5f

// ---------------- scratch (static device allocations; no cudaMalloc) --------
__device__ float g_x0 [BATCH*C*N];   // x0 (erased), later reused as x1e
__device__ float g_x1 [BATCH*C*N];   // x1seq
__device__ float g_At [BATCH*N*O];   // neighbor-term GEMM, [b][j][o]
__device__ float g_Ct [BATCH*N*O];   // center-term GEMM + bias, [b][i][o]
__device__ float g_y  [BATCH*N*O];   // edge-pooled features [b][i][o]
__device__ int   g_idx [BATCH*N*KM];
__device__ int   g_idx8[BATCH*N*KC];
__device__ float g_f  [BATCH*N];
__device__ float g_em [BATCH*N];
__device__ float g_smx[BATCH*N];
__device__ float g_res [BATCH*C];
__device__ float g_yvec[BATCH*C];
__device__ float g_q   [BATCH*C];
__device__ float g_xv  [BATCH*O];
__device__ float g_wAt [2][C*O];
__device__ float g_wDt [2][C*O];
__device__ float g_bias[2][O];

// ---------------- packed f32x2 FMA (FFMA2) ---------------------------------
__device__ __forceinline__ unsigned long long fma2(unsigned long long a,
                                                   unsigned long long b,
                                                   unsigned long long c) {
    unsigned long long d;
    asm("fma.rn.f32x2 %0, %1, %2, %3;" : "=l"(d) : "l"(a), "l"(b), "l"(c));
    return d;
}
__device__ __forceinline__ float2 unpk(unsigned long long a) {
    float2 r;
    asm("mov.b64 {%0,%1}, %2;" : "=f"(r.x), "=f"(r.y) : "l"(a));
    return r;
}

// ---------------- KNN: block per b, 512 threads ------------------------------
// smem: points transposed [512][68] (pad=68 for bank spread, norm in slot 64)
// plus a 64x65 staging tile for the conflict-free transpose.
#define PTS_STRIDE 68
#define KNN_SMEM_FLOATS (N*PTS_STRIDE + 64*65)
#define KNN_SMEM_BYTES  (KNN_SMEM_FLOATS*4)

template<int K>
__global__ __launch_bounds__(512, 1)
void knn_kernel(const float* __restrict__ x, int* __restrict__ idx_out) {
    extern __shared__ float sh[];
    float* sp   = sh;                 // [512][68]
    float* tile = sh + N*PTS_STRIDE;  // [64][65]
    const int b  = blockIdx.x;
    const int t  = threadIdx.x;
    const float* xb = x + (size_t)b * C * N;

    // transpose [64][512] -> [512][68] via 64x64 tiles
    for (int jc = 0; jc < 8; ++jc) {
        for (int e = t; e < 64*64; e += 512) {
            int c = e >> 6, jj = e & 63;
            tile[c*65 + jj] = xb[c*N + jc*64 + jj];
        }
        __syncthreads();
        for (int e = t; e < 64*64; e += 512) {
            int c = e & 63, jj = e >> 6;
            sp[(jc*64 + jj)*PTS_STRIDE + c] = tile[c*65 + jj];
        }
        __syncthreads();
    }
    // norms into padding slot 64
    {
        const float* p = sp + t*PTS_STRIDE;
        float s = 0.f;
        #pragma unroll
        for (int c = 0; c < C; ++c) s += p[c]*p[c];
        sp[t*PTS_STRIDE + 64] = s;
    }
    __syncthreads();

    // query -> registers (32 x f32x2 = 64 floats)
    const int i = t;
    ulonglong2 q[16];
    {
        const ulonglong2* qp = reinterpret_cast<const ulonglong2*>(sp + i*PTS_STRIDE);
        #pragma unroll
        for (int u = 0; u < 16; ++u) q[u] = qp[u];
    }

    float vals[K];
    int   inds[K];
    #pragma unroll
    for (int s = 0; s < K; ++s) { vals[s] = -INFINITY; inds[s] = 0; }

    for (int j = 0; j < N; ++j) {
        const ulonglong2* pp = reinterpret_cast<const ulonglong2*>(sp + j*PTS_STRIDE);
        unsigned long long a0 = 0ull, a1 = 0ull;
        #pragma unroll
        for (int u = 0; u < 16; ++u) {
            ulonglong2 pv = pp[u];
            a0 = fma2(q[u].x, pv.x, a0);
            a1 = fma2(q[u].y, pv.y, a1);
        }
        float2 f0 = unpk(a0), f1 = unpk(a1);
        float dot = (f0.x + f0.y) + (f1.x + f1.y);
        // ordering-equivalent distance: 2*dot - ||pj||^2  (constant +||pi||^2 shift)
        float d = 2.f*dot - sp[j*PTS_STRIDE + 64];
        if (d > vals[K-1]) {               // strict >: keeps earlier index on ties
            vals[K-1] = d; inds[K-1] = j;
            #pragma unroll
            for (int s = K-1; s > 0; --s) {
                if (vals[s] > vals[s-1]) {
                    float tv = vals[s]; vals[s] = vals[s-1]; vals[s-1] = tv;
                    int   ti = inds[s]; inds[s] = inds[s-1]; inds[s-1] = ti;
                }
            }
        }
    }
    int* o = idx_out + ((size_t)b*N + i)*K;
    #pragma unroll
    for (int s = 0; s < K; ++s) o[s] = inds[s];
}

// ---------------- weight prep: fold BN scale into conv ----------------------
__global__ void k_prep_w(const float* __restrict__ w, const float* __restrict__ g,
                         const float* __restrict__ bb, const float* __restrict__ m,
                         const float* __restrict__ v,
                         float* __restrict__ wAt, float* __restrict__ wDt,
                         float* __restrict__ bias) {
    int e = blockIdx.x*blockDim.x + threadIdx.x;
    if (e >= C*O) return;
    int o = e & 63, c = e >> 6;
    float s = g[o] / sqrtf(v[o] + EPSBN);
    float wa = w[o*128 + c];
    wAt[c*O + o] = wa * s;
    wDt[c*O + o] = (w[o*128 + 64 + c] - wa) * s;
    if (c == 0) bias[o] = bb[o] - m[o]*s;
}

// ---------------- res = mean_n x   (block per b) -----------------------------
__global__ void k_mean(const float* __restrict__ x, float* __restrict__ res) {
    __shared__ float sp[512];
    int b = blockIdx.x, t = threadIdx.x;
    int c = t & 63, seg = t >> 6;
    const float* p = x + ((size_t)b*C + c)*N + seg*64;
    float s = 0.f;
    #pragma unroll 8
    for (int i = 0; i < 64; ++i) s += p[i];
    sp[t] = s; __syncthreads();
    if (seg == 0) {
        float tot = 0.f;
        #pragma unroll
        for (int k = 0; k < 8; ++k) tot += sp[k*64 + c];
        res[b*C + c] = tot * (1.f/N);
    }
}

// ---------------- res = sum_n x*sm  (block per b) ----------------------------
__global__ void k_res_w(const float* __restrict__ x, const float* __restrict__ smw,
                        float* __restrict__ res) {
    __shared__ float ssm[N];
    __shared__ float sp[512];
    int b = blockIdx.x, t = threadIdx.x;
    ssm[t] = smw[b*N + t];
    __syncthreads();
    int c = t & 63, seg = t >> 6;
    const float* p = x + ((size_t)b*C + c)*N + seg*64;
    float s = 0.f;
    #pragma unroll 8
    for (int i = 0; i < 64; ++i) s += p[i]*ssm[seg*64 + i];
    sp[t] = s; __syncthreads();
    if (seg == 0) {
        float tot = 0.f;
        #pragma unroll
        for (int k = 0; k < 8; ++k) tot += sp[k*64 + c];
        res[b*C + c] = tot;
    }
}

// ---------------- erase vector: BN(W_e @ res + b_e) --------------------------
__global__ void k_erasevec(const float* __restrict__ res, const float* __restrict__ w,
                           const float* __restrict__ be, const float* __restrict__ ge,
                           const float* __restrict__ bee, const float* __restrict__ me,
                           const float* __restrict__ ve, float* __restrict__ yv) {
    __shared__ float sr[C];
    int b = blockIdx.x, o = threadIdx.x;
    sr[o] = res[b*C + o];
    __syncthreads();
    float a = 0.f;
    #pragma unroll 8
    for (int c = 0; c < C; ++c) a += w[o*C + c]*sr[c];
    a += be[o];
    float s = ge[o] / sqrtf(ve[o] + EPSBN);
    yv[b*C + o] = (a - me[o])*s + bee[o];
}

// ---------------- x_out = x*mask + yvec (broadcast) --------------------------
__global__ void k_erase_apply(const float* __restrict__ x, const float* __restrict__ em,
                              const float* __restrict__ yv, float* __restrict__ out) {
    int t = blockIdx.x*blockDim.x + threadIdx.x;
    if (t >= BATCH*C*N) return;
    int i = t & (N-1); int bc = t >> 9; int c = bc & 63; int b = bc >> 6;
    float m = em ? em[b*N + i] : 1.f;
    out[t] = x[t]*m + yv[b*C + c];
}

// ---------------- build x1seq (time shift) -----------------------------------
__global__ void k_build_x1(const float* __restrict__ x, float* __restrict__ x1) {
    int t = blockIdx.x*blockDim.x + threadIdx.x;
    if (t >= BATCH*C*N) return;
    int r = t & (C*N - 1); int bt = t >> 15;
    int b0 = bt / 12, tt = bt % 12;
    int t2 = tt + 1; if (t2 > 11) t2 = 11;
    x1[t] = x[((size_t)(b0*12 + t2) << 15) + r];
}

// ---------------- A/D GEMMs: [64x64] x [64x512] per b ------------------------
__global__ void k_gemm(const float* __restrict__ x, const float* __restrict__ wAt,
                       const float* __restrict__ wDt, const float* __restrict__ bias,
                       float* __restrict__ At, float* __restrict__ Ct) {
    __shared__ float xs [C*64];
    __shared__ float swA[C*O];
    __shared__ float swD[C*O];
    int b = blockIdx.y, jc = blockIdx.x;
    int t = threadIdx.x;
    for (int e = t; e < C*O; e += 256) { swA[e] = wAt[e]; swD[e] = wDt[e]; }
    const float* xb = x + (size_t)b*C*N + jc*64;
    for (int e = t; e < C*64; e += 256) {
        int c = e >> 6, jj = e & 63;
        xs[c*64 + jj] = xb[c*N + jj];
    }
    __syncthreads();
    int og = t & 15, jt = t >> 4;
    float a[4][4] = {}, d[4][4] = {};
    #pragma unroll 4
    for (int c = 0; c < C; ++c) {
        float4 wa = *(const float4*)(swA + c*O + og*4);
        float4 wd = *(const float4*)(swD + c*O + og*4);
        float4 xv = *(const float4*)(xs  + c*64 + jt*4);
        float xw[4]  = {xv.x, xv.y, xv.z, xv.w};
        float wav[4] = {wa.x, wa.y, wa.z, wa.w};
        float wdv[4] = {wd.x, wd.y, wd.z, wd.w};
        #pragma unroll
        for (int oo = 0; oo < 4; ++oo)
            #pragma unroll
            for (int jj = 0; jj < 4; ++jj) {
                a[oo][jj] += wav[oo]*xw[jj];
                d[oo][jj] += wdv[oo]*xw[jj];
            }
    }
    float bz[4];
    #pragma unroll
    for (int oo = 0; oo < 4; ++oo) bz[oo] = bias[og*4 + oo];
    int jbase = jc*64 + jt*4;
    #pragma unroll
    for (int jj = 0; jj < 4; ++jj) {
        float4 va = make_float4(a[0][jj], a[1][jj], a[2][jj], a[3][jj]);
        float4 vd = make_float4(d[0][jj]+bz[0], d[1][jj]+bz[1], d[2][jj]+bz[2], d[3][jj]+bz[3]);
        *(float4*)(At + ((size_t)b*N + jbase + jj)*O + og*4) = va;
        *(float4*)(Ct + ((size_t)b*N + jbase + jj)*O + og*4) = vd;
    }
}

// ---------------- edge pool: y[b][i][o] = lrelu(max_k A[jk][o] + Ct[i][o]) ----
#define EP_SMEM_BYTES (N*O*4 + N*KM*4)
template<int K>
__global__ __launch_bounds__(512, 1)
void k_edgepool(const float* __restrict__ At, const float* __restrict__ Ct,
                const int* __restrict__ idx, float* __restrict__ y) {
    extern __shared__ float sh[];
    float* sA = sh;                    // [512][64]
    int*   sI = (int*)(sh + N*O);      // [512][K]
    int b = blockIdx.x, t = threadIdx.x;
    {
        const float4* src = (const float4*)(At + (size_t)b*N*O);
        float4* dst = (float4*)sA;
        for (int e = t; e < N*O/4; e += 512) dst[e] = src[e];
        const int* isrc = idx + (size_t)b*N*K;
        for (int e = t; e < N*K; e += 512) sI[e] = isrc[e];
    }
    __syncthreads();
    int w = t >> 5, l = t & 31;
    for (int ii = 0; ii < 32; ++ii) {
        int i = w*32 + ii;
        float2 mx = make_float2(-INFINITY, -INFINITY);
        #pragma unroll
        for (int k = 0; k < K; ++k) {
            int jk = sI[i*K + k];
            float2 v = *(const float2*)(sA + jk*O + 2*l);
            mx.x = fmaxf(mx.x, v.x); mx.y = fmaxf(mx.y, v.y);
        }
        float2 ct = *(const float2*)(Ct + ((size_t)b*N + i)*O + 2*l);
        float vx = mx.x + ct.x, vy = mx.y + ct.y;
        vx = vx > 0.f ? vx : 0.2f*vx;
        vy = vy > 0.f ? vy : 0.2f*vy;
        *(float2*)(y + ((size_t)b*N + i)*O + 2*l) = make_float2(vx, vy);
    }
}

// ---------------- pool over n: max + mean -> out (and x0_vec) ---------------
__global__ void k_pool2(const float* __restrict__ y, float* __restrict__ out,
                        float* __restrict__ xv, int add) {
    __shared__ float smax[512], ssum[512];
    int b = blockIdx.x, t = threadIdx.x;
    int o = t & 63, seg = t >> 6;
    float mx = -INFINITY, sm = 0.f;
    const float* p = y + (size_t)b*N*O + seg*64*O + o;
    #pragma unroll 4
    for (int i = 0; i < 64; ++i) { float v = p[i*O]; mx = fmaxf(mx, v); sm += v; }
    smax[t] = mx; ssum[t] = sm;
    __syncthreads();
    if (seg == 0) {
        #pragma unroll
        for (int k = 1; k < 8; ++k) { mx = fmaxf(mx, smax[k*64 + o]); sm += ssum[k*64 + o]; }
        float mean = sm * (1.f/N);
        if (add) { out[b*128 + o] += mx; out[b*128 + 64 + o] += mean; }
        else     { out[b*128 + o]  = mx; out[b*128 + 64 + o]  = mean;
                   if (xv) xv[b*O + o] = mx; }
    }
}

// ---------------- q = w_reduce @ x0_vec --------------------------------------
__global__ void k_q(const float* __restrict__ xv, const float* __restrict__ wr,
                    float* __restrict__ q) {
    __shared__ float sx[O];
    int b = blockIdx.x, o = threadIdx.x;
    sx[o] = xv[b*O + o];
    __syncthreads();
    float a = 0.f;
    #pragma unroll 8
    for (int c = 0; c < C; ++c) a += wr[o*C + c]*sx[c];
    q[b*C + o] = a;
}

// ---------------- f[b][i] = dot(q, x1[:,i]) / 8 -----------------------------
__global__ void k_f(const float* __restrict__ x1, const float* __restrict__ q,
                    float* __restrict__ f) {
    __shared__ float sq[C];
    int b = blockIdx.x, t = threadIdx.x;
    if (t < C) sq[t] = q[b*C + t];
    __syncthreads();
    const float* p = x1 + (size_t)b*C*N + t;
    float a = 0.f;
    #pragma unroll 8
    for (int c = 0; c < C; ++c) a += sq[c]*p[c*N];
    f[b*N + t] = a * 0.125f;
}

// ---------------- fk + argmax + erase-mask -----------------------------------
__global__ void k_fk_mask(const float* __restrict__ f, const int* __restrict__ idx8,
                          float* __restrict__ em) {
    __shared__ float sf[N];
    __shared__ float sv[512];
    __shared__ int   si[512];
    int b = blockIdx.x, t = threadIdx.x;
    sf[t] = f[b*N + t];
    __syncthreads();
    float fk = sf[t];
    const int* ip = idx8 + ((size_t)b*N + t)*KC;
    #pragma unroll
    for (int k = 0; k < KC; ++k) fk += sf[ip[k]];
    sv[t] = fk; si[t] = t;
    __syncthreads();
    for (int s = 256; s > 0; s >>= 1) {
        if (t < s) {
            float v2 = sv[t+s]; int i2 = si[t+s];
            if (v2 > sv[t] || (v2 == sv[t] && i2 < si[t])) { sv[t] = v2; si[t] = i2; }
        }
        __syncthreads();
    }
    int index = si[0];
    em[b*N + t] = 1.f;
    __syncthreads();
    if (t < KC) em[b*N + idx8[((size_t)b*N + index)*KC + t]] = 0.f;
    if (t == KC) em[b*N + index] = 0.f;
}

// ---------------- masked softmax ---------------------------------------------
__global__ void k_softmax(const float* __restrict__ f, const float* __restrict__ em,
                          float* __restrict__ smo) {
    __shared__ float red[512];
    int b = blockIdx.x, t = threadIdx.x;
    float s = f[b*N + t] - (1.f - em[b*N + t])*1e8f;
    red[t] = s;
    __syncthreads();
    for (int st = 256; st > 0; st >>= 1) {
        if (t < st) red[t] = fmaxf(red[t], red[t+st]);
        __syncthreads();
    }
    float mx = red[0];
    __syncthreads();
    float e = expf(s - mx);
    red[t] = e;
    __syncthreads();
    for (int st = 256; st > 0; st >>= 1) {
        if (t < st) red[t] += red[t+st];
        __syncthreads();
    }
    smo[b*N + t] = e / red[0];
}

// =============================================================================
extern "C" void kernel_launch(void* const* d_in, const int* in_sizes, int n_in,
                              void* d_out, int out_size) {
    const float* x        = (const float*)d_in[0];
    const float* w_reduce = (const float*)d_in[1];
    const float* w_erase  = (const float*)d_in[2];
    const float* b_erase  = (const float*)d_in[3];
    const float* g_erase  = (const float*)d_in[4];
    const float* be_erase = (const float*)d_in[5];
    const float* m_erase  = (const float*)d_in[6];
    const float* v_erase  = (const float*)d_in[7];
    const float* w0 = (const float*)d_in[8];
    const float* g0 = (const float*)d_in[9];
    const float* b0 = (const float*)d_in[10];
    const float* m0 = (const float*)d_in[11];
    const float* v0 = (const float*)d_in[12];
    const float* w1 = (const float*)d_in[13];
    const float* g1 = (const float*)d_in[14];
    const float* b1 = (const float*)d_in[15];
    const float* m1 = (const float*)d_in[16];
    const float* v1 = (const float*)d_in[17];
    float* out = (float*)d_out;

    float *p_x0, *p_x1, *p_At, *p_Ct, *p_y, *p_f, *p_em, *p_sm;
    float *p_res, *p_yvec, *p_q, *p_xv, *p_wAt, *p_wDt, *p_bias;
    int *p_idx, *p_idx8;
    cudaGetSymbolAddress((void**)&p_x0,  g_x0);
    cudaGetSymbolAddress((void**)&p_x1,  g_x1);
    cudaGetSymbolAddress((void**)&p_At,  g_At);
    cudaGetSymbolAddress((void**)&p_Ct,  g_Ct);
    cudaGetSymbolAddress((void**)&p_y,   g_y);
    cudaGetSymbolAddress((void**)&p_idx, g_idx);
    cudaGetSymbolAddress((void**)&p_idx8,g_idx8);
    cudaGetSymbolAddress((void**)&p_f,   g_f);
    cudaGetSymbolAddress((void**)&p_em,  g_em);
    cudaGetSymbolAddress((void**)&p_sm,  g_smx);
    cudaGetSymbolAddress((void**)&p_res, g_res);
    cudaGetSymbolAddress((void**)&p_yvec,g_yvec);
    cudaGetSymbolAddress((void**)&p_q,   g_q);
    cudaGetSymbolAddress((void**)&p_xv,  g_xv);
    cudaGetSymbolAddress((void**)&p_wAt, g_wAt);
    cudaGetSymbolAddress((void**)&p_wDt, g_wDt);
    cudaGetSymbolAddress((void**)&p_bias,g_bias);

    cudaFuncSetAttribute(knn_kernel<KM>, cudaFuncAttributeMaxDynamicSharedMemorySize, KNN_SMEM_BYTES);
    cudaFuncSetAttribute(knn_kernel<KC>, cudaFuncAttributeMaxDynamicSharedMemorySize, KNN_SMEM_BYTES);
    cudaFuncSetAttribute(k_edgepool<KM>, cudaFuncAttributeMaxDynamicSharedMemorySize, EP_SMEM_BYTES);

    const int ELEMS = BATCH*C*N;
    const int EBLK  = (ELEMS + 255)/256;

    // weight prep (both branches)
    k_prep_w<<<16, 256>>>(w0, g0, b0, m0, v0, p_wAt,        p_wDt,        p_bias);
    k_prep_w<<<16, 256>>>(w1, g1, b1, m1, v1, p_wAt + C*O,  p_wDt + C*O,  p_bias + O);

    // ---- erase #1 (uniform) + x1seq ----
    k_mean<<<BATCH, 512>>>(x, p_res);
    k_erasevec<<<BATCH, 64>>>(p_res, w_erase, b_erase, g_erase, be_erase, m_erase, v_erase, p_yvec);
    k_erase_apply<<<EBLK, 256>>>(x, nullptr, p_yvec, p_x0);
    k_build_x1<<<EBLK, 256>>>(x, p_x1);

    // ---- branch 0 ----
    knn_kernel<KM><<<BATCH, 512, KNN_SMEM_BYTES>>>(p_x0, p_idx);
    k_gemm<<<dim3(8, BATCH), 256>>>(p_x0, p_wAt, p_wDt, p_bias, p_At, p_Ct);
    k_edgepool<KM><<<BATCH, 512, EP_SMEM_BYTES>>>(p_At, p_Ct, p_idx, p_y);
    k_pool2<<<BATCH, 512>>>(p_y, out, p_xv, 0);

    // ---- correlation / erase #2 ----
    k_q<<<BATCH, 64>>>(p_xv, w_reduce, p_q);
    k_f<<<BATCH, 512>>>(p_x1, p_q, p_f);
    knn_kernel<KC><<<BATCH, 512, KNN_SMEM_BYTES>>>(p_x1, p_idx8);
    k_fk_mask<<<BATCH, 512>>>(p_f, p_idx8, p_em);
    k_softmax<<<BATCH, 512>>>(p_f, p_em, p_sm);
    k_res_w<<<BATCH, 512>>>(p_x1, p_sm, p_res);
    k_erasevec<<<BATCH, 64>>>(p_res, w_erase, b_erase, g_erase, be_erase, m_erase, v_erase, p_yvec);
    k_erase_apply<<<EBLK, 256>>>(p_x1, p_em, p_yvec, p_x0);   // reuse g_x0 as x1e

    // ---- branch 1 ----
    knn_kernel<KM><<<BATCH, 512, KNN_SMEM_BYTES>>>(p_x0, p_idx);
    k_gemm<<<dim3(8, BATCH), 256>>>(p_x0, p_wAt + C*O, p_wDt + C*O, p_bias + O, p_At, p_Ct);
    k_edgepool<KM><<<BATCH, 512, EP_SMEM_BYTES>>>(p_At, p_Ct, p_idx, p_y);
    k_pool2<<<BATCH, 512>>>(p_y, out, nullptr, 1);
}